// round 15
// baseline (speedup 1.0000x reference)
#include <cuda_runtime.h>
#include <cuda_bf16.h>
#include <cstdint>
#include <math.h>

#define B_   32
#define N_   256
#define E_   512
#define H_   8
#define D_   64
#define ID_  8
#define KDIM 512

// ---------------- device-global scratch (alloc-free), all bf16 hi/lo ----------------
__device__ __nv_bfloat16 g_xhi[(size_t)B_*N_*E_],  g_xlo[(size_t)B_*N_*E_];
__device__ __nv_bfloat16 g_wqhi[(size_t)3*E_*E_],  g_wqlo[(size_t)3*E_*E_];
__device__ __nv_bfloat16 g_wohi[(size_t)E_*E_],    g_wolo[(size_t)E_*E_];
__device__ __nv_bfloat16 g_qhi[(size_t)B_*H_*N_*D_], g_qlo[(size_t)B_*H_*N_*D_];
__device__ __nv_bfloat16 g_khi[(size_t)B_*H_*N_*D_], g_klo[(size_t)B_*H_*N_*D_];
__device__ __nv_bfloat16 g_vhi[(size_t)B_*H_*N_*D_], g_vlo[(size_t)B_*H_*N_*D_];
__device__ __nv_bfloat16 g_ohi[(size_t)B_*N_*E_],  g_olo[(size_t)B_*N_*E_];

// ================= helpers =================
__device__ __forceinline__ uint32_t smem_u32(const void* p) {
    uint32_t a;
    asm("{ .reg .u64 t; cvta.to.shared.u64 t, %1; cvt.u32.u64 %0, t; }" : "=r"(a) : "l"(p));
    return a;
}
__device__ __forceinline__ void ldsm4(uint32_t* r, uint32_t addr) {
    asm volatile("ldmatrix.sync.aligned.m8n8.x4.shared.b16 {%0,%1,%2,%3}, [%4];"
        : "=r"(r[0]), "=r"(r[1]), "=r"(r[2]), "=r"(r[3]) : "r"(addr));
}
__device__ __forceinline__ void ldsm4t(uint32_t* r, uint32_t addr) {
    asm volatile("ldmatrix.sync.aligned.m8n8.x4.trans.shared.b16 {%0,%1,%2,%3}, [%4];"
        : "=r"(r[0]), "=r"(r[1]), "=r"(r[2]), "=r"(r[3]) : "r"(addr));
}
__device__ __forceinline__ void mma16816(float* c, const uint32_t* a, const uint32_t* b) {
    asm volatile("mma.sync.aligned.m16n8k16.row.col.f32.bf16.bf16.f32 "
        "{%0,%1,%2,%3}, {%4,%5,%6,%7}, {%8,%9}, {%0,%1,%2,%3};"
        : "+f"(c[0]), "+f"(c[1]), "+f"(c[2]), "+f"(c[3])
        : "r"(a[0]), "r"(a[1]), "r"(a[2]), "r"(a[3]), "r"(b[0]), "r"(b[1]));
}
__device__ __forceinline__ void split2(float x, float y,
                                       __nv_bfloat162& hi, __nv_bfloat162& lo) {
    __nv_bfloat16 hx = __float2bfloat16(x), hy = __float2bfloat16(y);
    hi.x = hx; hi.y = hy;
    lo.x = __float2bfloat16(x - __bfloat162float(hx));
    lo.y = __float2bfloat16(y - __bfloat162float(hy));
}
__device__ __forceinline__ void pksplit(float x, float y, uint32_t& hi, uint32_t& lo) {
    __nv_bfloat162 H, L;
    split2(x, y, H, L);
    hi = *reinterpret_cast<uint32_t*>(&H);
    lo = *reinterpret_cast<uint32_t*>(&L);
}
__device__ __forceinline__ float dot8(float4 a, float4 b, const float* w) {
    return a.x*w[0] + a.y*w[1] + a.z*w[2] + a.w*w[3]
         + b.x*w[4] + b.y*w[5] + b.z*w[6] + b.w*w[7];
}
#define CP16(dst, src) asm volatile("cp.async.cg.shared.global [%0], [%1], 16;" :: "r"(dst), "l"(src))
#define CPCOMMIT()     asm volatile("cp.async.commit_group;" ::: "memory")
#define CPWAIT0()      asm volatile("cp.async.wait_group 0;" ::: "memory")

// ---------------- prep: fp32->bf16 hi/lo split ONLY (bias fused into attn) ----------------
#define NX4 (B_*N_*E_/4)
#define NWQ4 (3*E_*E_/4)
#define NWO4 (E_*E_/4)
#define CONV_BLOCKS ((NX4+NWQ4+NWO4)/256)

__global__ void prep_kernel(const float4* __restrict__ x4,
                            const float4* __restrict__ wq4,
                            const float4* __restrict__ wo4) {
    int idx = blockIdx.x * blockDim.x + threadIdx.x;
    const float4* src;
    __nv_bfloat162 *hi, *lo;
    int li;
    if (idx < NX4)           { src = x4;  li = idx;              hi = (__nv_bfloat162*)g_xhi;  lo = (__nv_bfloat162*)g_xlo; }
    else if (idx < NX4+NWQ4) { src = wq4; li = idx - NX4;        hi = (__nv_bfloat162*)g_wqhi; lo = (__nv_bfloat162*)g_wqlo; }
    else                     { src = wo4; li = idx - NX4 - NWQ4; hi = (__nv_bfloat162*)g_wohi; lo = (__nv_bfloat162*)g_wolo; }
    float4 v = src[li];
    __nv_bfloat162 h0, l0, h1, l1;
    split2(v.x, v.y, h0, l0); split2(v.z, v.w, h1, l1);
    hi[li*2] = h0; hi[li*2+1] = h1;
    lo[li*2] = l0; lo[li*2+1] = l1;
}

// ============ HMMA GEMM, pre-split bf16, 2-stage cp.async, 2 CTAs/SM ============
#define TK 32
#define NKS (KDIM/TK)
#define MAT_B (128*40*2)
#define STG_B (4*MAT_B)
#define GEMM_SMEM (2*STG_B)

__global__ __launch_bounds__(256, 2)
void gemm_mma(const float* __restrict__ bias, int mode, float* __restrict__ out) {
    extern __shared__ char dsm[];
    const int t    = threadIdx.x;
    const int lane = t & 31;
    const int wid  = t >> 5;
    const int warpM = wid >> 2;
    const int warpN = wid & 3;
    const int rowBase = blockIdx.y * 128;
    const int colBase = blockIdx.x * 128;
    const uint32_t smb = smem_u32(dsm);

    const __nv_bfloat16 *Ah, *Al, *Wh, *Wl;
    if (mode == 0) { Ah = g_xhi; Al = g_xlo; Wh = g_wqhi; Wl = g_wqlo; }
    else           { Ah = g_ohi; Al = g_olo; Wh = g_wohi; Wl = g_wolo; }

    float acc[4][4][4];
    #pragma unroll
    for (int i = 0; i < 4; i++)
        #pragma unroll
        for (int j = 0; j < 4; j++)
            #pragma unroll
            for (int e = 0; e < 4; e++) acc[i][j][e] = 0.f;

    auto issue = [&](int s) {
        int k0 = s * TK;
        uint32_t st = smb + (s & 1)*STG_B;
        #pragma unroll
        for (int l = 0; l < 2; l++) {
            int f = t + l*256;
            int r = f >> 2, c = f & 3;
            uint32_t doff = (uint32_t)(r*80 + c*16);
            CP16(st + doff,           Ah + (size_t)(rowBase + r)*KDIM + k0 + c*8);
            CP16(st + MAT_B + doff,   Al + (size_t)(rowBase + r)*KDIM + k0 + c*8);
            CP16(st + 2*MAT_B + doff, Wh + (size_t)(colBase + r)*KDIM + k0 + c*8);
            CP16(st + 3*MAT_B + doff, Wl + (size_t)(colBase + r)*KDIM + k0 + c*8);
        }
    };

    issue(0);
    CPCOMMIT();

    for (int ks = 0; ks < NKS; ks++) {
        CPWAIT0();
        __syncthreads();
        if (ks + 1 < NKS) { issue(ks + 1); CPCOMMIT(); }

        uint32_t stg = smb + (ks & 1)*STG_B;
        #pragma unroll
        for (int k16 = 0; k16 < 2; k16++) {
            int colb = k16 * 16;
            uint32_t whi[4][2], wlo[4][2];
            {
                int l8  = lane & 7, sel = lane >> 3;
                #pragma unroll
                for (int np = 0; np < 2; np++) {
                    int wrow = warpN*32 + np*16 + (sel >> 1)*8 + l8;
                    int wcol = colb + (sel & 1)*8;
                    uint32_t off = (uint32_t)(wrow*80 + wcol*2);
                    uint32_t r[4];
                    ldsm4(r, stg + 2*MAT_B + off);
                    whi[np*2+0][0]=r[0]; whi[np*2+0][1]=r[1];
                    whi[np*2+1][0]=r[2]; whi[np*2+1][1]=r[3];
                    ldsm4(r, stg + 3*MAT_B + off);
                    wlo[np*2+0][0]=r[0]; wlo[np*2+0][1]=r[1];
                    wlo[np*2+1][0]=r[2]; wlo[np*2+1][1]=r[3];
                }
            }
            int r8 = lane & 7, half = (lane >> 3) & 1, kk = lane >> 4;
            #pragma unroll
            for (int mi = 0; mi < 4; mi++) {
                int arow = warpM*64 + mi*16 + half*8 + r8;
                int acol = colb + kk*8;
                uint32_t off = (uint32_t)(arow*80 + acol*2);
                uint32_t a[4];
                ldsm4(a, stg + off);
                #pragma unroll
                for (int ni = 0; ni < 4; ni++) mma16816(acc[mi][ni], a, whi[ni]);
                #pragma unroll
                for (int ni = 0; ni < 4; ni++) mma16816(acc[mi][ni], a, wlo[ni]);
                ldsm4(a, stg + MAT_B + off);
                #pragma unroll
                for (int ni = 0; ni < 4; ni++) mma16816(acc[mi][ni], a, whi[ni]);
            }
        }
    }

    const int gID = lane >> 2, tg = lane & 3;
    #pragma unroll
    for (int mi = 0; mi < 4; mi++) {
        #pragma unroll
        for (int ni = 0; ni < 4; ni++) {
            #pragma unroll
            for (int e2 = 0; e2 < 2; e2++) {
                int r = rowBase + warpM*64 + mi*16 + gID + e2*8;
                int c = colBase + warpN*32 + ni*8 + tg*2;
                float v0 = acc[mi][ni][e2*2+0] + __ldg(bias + c);
                float v1 = acc[mi][ni][e2*2+1] + __ldg(bias + c + 1);
                if (mode == 0) {
                    int bb = r >> 8, n = r & 255;
                    int sec = c >> 9;
                    int jj  = c & 511;
                    int h = jj >> 6, d = jj & 63;
                    size_t dst = ((size_t)((bb*H_ + h)*N_ + n))*D_ + d;
                    __nv_bfloat162 hi, lo;
                    if (sec == 0) {
                        split2(v0 * 0.125f, v1 * 0.125f, hi, lo);
                        *(__nv_bfloat162*)(g_qhi + dst) = hi;
                        *(__nv_bfloat162*)(g_qlo + dst) = lo;
                    } else if (sec == 1) {
                        split2(v0, v1, hi, lo);
                        *(__nv_bfloat162*)(g_khi + dst) = hi;
                        *(__nv_bfloat162*)(g_klo + dst) = lo;
                    } else {
                        split2(v0, v1, hi, lo);
                        *(__nv_bfloat162*)(g_vhi + dst) = hi;
                        *(__nv_bfloat162*)(g_vlo + dst) = lo;
                    }
                } else {
                    out[(size_t)r*E_ + c]     = v0;
                    out[(size_t)r*E_ + c + 1] = v1;
                }
            }
        }
    }
}

// ======== attention: online softmax, 2 key chunks, 2 CTAs/SM; bias fused from U ========
#define KP 72
#define AT_KHI 0
#define AT_KLO 18432
#define AT_VHI 36864
#define AT_VLO 55296
#define AT_QHI 73728
#define AT_QLO 92160
#define ATTN_SMEM 110592

__global__ __launch_bounds__(256, 2)
void attn_kernel(const float* __restrict__ U,
                 const float* __restrict__ w_u,
                 const float* __restrict__ b_u) {
    extern __shared__ char asm_[];
    const int bh = blockIdx.x;
    const int q0 = blockIdx.y << 7;
    const int t  = threadIdx.x;
    const int lane = t & 31;
    const int wid  = t >> 5;
    const int gID = lane >> 2, tg = lane & 3;
    const int b  = bh >> 3, h = bh & 7;
    const uint32_t smb = smem_u32(asm_);

    const uint4* khi = (const uint4*)(g_khi + (size_t)bh * N_ * D_);
    const uint4* klo = (const uint4*)(g_klo + (size_t)bh * N_ * D_);
    const uint4* vhi = (const uint4*)(g_vhi + (size_t)bh * N_ * D_);
    const uint4* vlo = (const uint4*)(g_vlo + (size_t)bh * N_ * D_);
    const uint4* qhi = (const uint4*)(g_qhi + (size_t)bh * N_ * D_ + (size_t)q0 * D_);
    const uint4* qlo = (const uint4*)(g_qlo + (size_t)bh * N_ * D_ + (size_t)q0 * D_);

    // per-head u-proj weights
    float wv[8];
    #pragma unroll
    for (int i = 0; i < 8; i++) wv[i] = __ldg(w_u + h*ID_ + i);
    const float bu = __ldg(b_u + h);

    for (int f = t; f < 1024; f += 256) {
        int row = f >> 3, c8 = f & 7;
        int off = row*144 + c8*16;
        *(uint4*)(asm_ + AT_QHI + off) = qhi[f];
        *(uint4*)(asm_ + AT_QLO + off) = qlo[f];
        *(uint4*)(asm_ + AT_KHI + off) = khi[f];
        *(uint4*)(asm_ + AT_KLO + off) = klo[f];
        *(uint4*)(asm_ + AT_VHI + off) = vhi[f];
        *(uint4*)(asm_ + AT_VLO + off) = vlo[f];
    }
    __syncthreads();

    const int l8 = lane & 7, sel = lane >> 3;
    const int r8 = lane & 7, halfq = (lane >> 3) & 1, k8 = lane >> 4;

    float oacc[8][4];
    #pragma unroll
    for (int j = 0; j < 8; j++)
        #pragma unroll
        for (int e = 0; e < 4; e++) oacc[j][e] = 0.f;
    float m_run[2] = { -1e30f, -1e30f };
    float s_run[2] = { 0.f, 0.f };

    #pragma unroll 1
    for (int c = 0; c < 2; c++) {
        float acc[16][4];
        #pragma unroll
        for (int j = 0; j < 16; j++)
            #pragma unroll
            for (int e = 0; e < 4; e++) acc[j][e] = 0.f;

        #pragma unroll
        for (int kk = 0; kk < 4; kk++) {
            int arow = wid*16 + halfq*8 + r8;
            int acol = kk*16 + k8*8;
            uint32_t aoff = (uint32_t)((arow*KP + acol)*2);
            uint32_t ahi[4], alo[4];
            ldsm4(ahi, smb + AT_QHI + aoff);
            ldsm4(alo, smb + AT_QLO + aoff);
            #pragma unroll
            for (int np = 0; np < 8; np++) {
                int wrow = np*16 + (sel >> 1)*8 + l8;
                int wcol = kk*16 + (sel & 1)*8;
                uint32_t koff = (uint32_t)((wrow*KP + wcol)*2);
                uint32_t kf[4];
                ldsm4(kf, smb + AT_KHI + koff);
                mma16816(acc[np*2+0], ahi, kf);
                mma16816(acc[np*2+1], ahi, kf + 2);
                mma16816(acc[np*2+0], alo, kf);
                mma16816(acc[np*2+1], alo, kf + 2);
                ldsm4(kf, smb + AT_KLO + koff);
                mma16816(acc[np*2+0], ahi, kf);
                mma16816(acc[np*2+1], ahi, kf + 2);
            }
        }

        // ---- bias computed on the fly from U: bias = U[b,r,c,:]·w_u[h,:] + b_u[h] ----
        {
            int r0 = q0 + wid*16 + gID;
            int cb = c*128;
            const float* Ub0 = U + (((size_t)b*N_ + r0    )*N_)*ID_;
            const float* Ub1 = U + (((size_t)b*N_ + r0 + 8)*N_)*ID_;
            #pragma unroll
            for (int nj = 0; nj < 16; nj++) {
                int cc = cb + nj*8 + tg*2;
                const float4* p0 = (const float4*)(Ub0 + (size_t)cc*ID_);
                const float4* p1 = (const float4*)(Ub1 + (size_t)cc*ID_);
                acc[nj][0] += bu + dot8(__ldg(p0+0), __ldg(p0+1), wv);
                acc[nj][1] += bu + dot8(__ldg(p0+2), __ldg(p0+3), wv);
                acc[nj][2] += bu + dot8(__ldg(p1+0), __ldg(p1+1), wv);
                acc[nj][3] += bu + dot8(__ldg(p1+2), __ldg(p1+3), wv);
            }
        }

        // ---- online softmax update ----
        float scale[2];
        #pragma unroll
        for (int h2 = 0; h2 < 2; h2++) {
            float m = m_run[h2];
            #pragma unroll
            for (int nj = 0; nj < 16; nj++) {
                m = fmaxf(m, acc[nj][h2*2+0]);
                m = fmaxf(m, acc[nj][h2*2+1]);
            }
            m = fmaxf(m, __shfl_xor_sync(0xffffffffu, m, 1));
            m = fmaxf(m, __shfl_xor_sync(0xffffffffu, m, 2));
            scale[h2] = __expf(m_run[h2] - m);
            float s = 0.f;
            #pragma unroll
            for (int nj = 0; nj < 16; nj++) {
                float p0 = __expf(acc[nj][h2*2+0] - m);
                float p1 = __expf(acc[nj][h2*2+1] - m);
                acc[nj][h2*2+0] = p0; acc[nj][h2*2+1] = p1;
                s += p0 + p1;
            }
            s += __shfl_xor_sync(0xffffffffu, s, 1);
            s += __shfl_xor_sync(0xffffffffu, s, 2);
            s_run[h2] = s_run[h2] * scale[h2] + s;
            m_run[h2] = m;
        }
        #pragma unroll
        for (int nd = 0; nd < 8; nd++) {
            oacc[nd][0] *= scale[0]; oacc[nd][1] *= scale[0];
            oacc[nd][2] *= scale[1]; oacc[nd][3] *= scale[1];
        }

        // ---- pack P in place ----
        uint32_t (*pk)[4] = reinterpret_cast<uint32_t(*)[4]>(acc);
        #pragma unroll
        for (int nj = 0; nj < 16; nj++) {
            float c0 = acc[nj][0], c1 = acc[nj][1], c2 = acc[nj][2], c3 = acc[nj][3];
            uint32_t h01, l01, h23, l23;
            pksplit(c0, c1, h01, l01);
            pksplit(c2, c3, h23, l23);
            pk[nj][0] = h01; pk[nj][1] = h23; pk[nj][2] = l01; pk[nj][3] = l23;
        }

        // ---- O += P V ----
        #pragma unroll
        for (int kc = 0; kc < 8; kc++) {
            uint32_t pa[4] = { pk[2*kc][0], pk[2*kc][1], pk[2*kc+1][0], pk[2*kc+1][1] };
            uint32_t pl[4] = { pk[2*kc][2], pk[2*kc][3], pk[2*kc+1][2], pk[2*kc+1][3] };
            #pragma unroll
            for (int ng = 0; ng < 4; ng++) {
                int vrow = kc*16 + (sel & 1)*8 + l8;
                int vcol = ng*16 + (sel >> 1)*8;
                uint32_t voff = (uint32_t)((vrow*KP + vcol)*2);
                uint32_t vh[4], vl[4];
                ldsm4t(vh, smb + AT_VHI + voff);
                ldsm4t(vl, smb + AT_VLO + voff);
                #pragma unroll
                for (int j = 0; j < 2; j++) {
                    mma16816(oacc[ng*2+j], pa, vh + j*2);
                    mma16816(oacc[ng*2+j], pa, vl + j*2);
                    mma16816(oacc[ng*2+j], pl, vh + j*2);
                }
            }
        }

        if (c == 0) {
            __syncthreads();
            for (int f = t; f < 1024; f += 256) {
                int row = f >> 3, c8 = f & 7;
                int off = row*144 + c8*16;
                *(uint4*)(asm_ + AT_KHI + off) = khi[1024 + f];
                *(uint4*)(asm_ + AT_KLO + off) = klo[1024 + f];
                *(uint4*)(asm_ + AT_VHI + off) = vhi[1024 + f];
                *(uint4*)(asm_ + AT_VLO + off) = vlo[1024 + f];
            }
            __syncthreads();
        }
    }

    // ---- normalize + store ----
    {
        float inv0 = 1.0f / s_run[0], inv1 = 1.0f / s_run[1];
        size_t row0 = (size_t)(b*N_ + q0 + wid*16 + gID) * E_ + h*D_;
        size_t row1 = row0 + 8*E_;
        #pragma unroll
        for (int nd = 0; nd < 8; nd++) {
            int cc = nd*8 + tg*2;
            __nv_bfloat162 h0, l0;
            split2(oacc[nd][0]*inv0, oacc[nd][1]*inv0, h0, l0);
            *(__nv_bfloat162*)(g_ohi + row0 + cc) = h0;
            *(__nv_bfloat162*)(g_olo + row0 + cc) = l0;
            split2(oacc[nd][2]*inv1, oacc[nd][3]*inv1, h0, l0);
            *(__nv_bfloat162*)(g_ohi + row1 + cc) = h0;
            *(__nv_bfloat162*)(g_olo + row1 + cc) = l0;
        }
    }
}

// ---------------- launcher (sequential, default stream) ----------------
extern "C" void kernel_launch(void* const* d_in, const int* in_sizes, int n_in,
                              void* d_out, int out_size) {
    const float* x     = (const float*)d_in[0];
    const float* U     = (const float*)d_in[1];
    const float* w_qkv = (const float*)d_in[2];
    const float* b_qkv = (const float*)d_in[3];
    const float* w_out = (const float*)d_in[4];
    const float* b_out = (const float*)d_in[5];
    const float* w_u   = (const float*)d_in[6];
    const float* b_u   = (const float*)d_in[7];
    float* out = (float*)d_out;

    cudaFuncSetAttribute(gemm_mma, cudaFuncAttributeMaxDynamicSharedMemorySize, GEMM_SMEM);
    cudaFuncSetAttribute(attn_kernel, cudaFuncAttributeMaxDynamicSharedMemorySize, ATTN_SMEM);

    prep_kernel<<<CONV_BLOCKS, 256>>>((const float4*)x,
                                      (const float4*)w_qkv,
                                      (const float4*)w_out);

    { dim3 g(1536/128, (B_*N_)/128); gemm_mma<<<g, 256, GEMM_SMEM>>>(b_qkv, 0, nullptr); }

    { dim3 g(B_*H_, 2); attn_kernel<<<g, 256, ATTN_SMEM>>>(U, w_u, b_u); }

    { dim3 g(512/128, (B_*N_)/128); gemm_mma<<<g, 256, GEMM_SMEM>>>(b_out, 1, out); }
}

// round 16
// speedup vs baseline: 1.2812x; 1.2812x over previous
#include <cuda_runtime.h>
#include <cuda_bf16.h>
#include <cstdint>
#include <math.h>

#define B_   32
#define N_   256
#define E_   512
#define H_   8
#define D_   64
#define ID_  8
#define KDIM 512

// ---------------- device-global scratch (alloc-free) ----------------
__device__ __nv_bfloat16 g_xhi[(size_t)B_*N_*E_],  g_xlo[(size_t)B_*N_*E_];
__device__ __nv_bfloat16 g_wqhi[(size_t)3*E_*E_],  g_wqlo[(size_t)3*E_*E_];
__device__ __nv_bfloat16 g_wohi[(size_t)E_*E_],    g_wolo[(size_t)E_*E_];
__device__ __nv_bfloat16 g_qhi[(size_t)B_*H_*N_*D_], g_qlo[(size_t)B_*H_*N_*D_];
__device__ __nv_bfloat16 g_khi[(size_t)B_*H_*N_*D_], g_klo[(size_t)B_*H_*N_*D_];
__device__ __nv_bfloat16 g_vhi[(size_t)B_*H_*N_*D_], g_vlo[(size_t)B_*H_*N_*D_];
__device__ __nv_bfloat16 g_ohi[(size_t)B_*N_*E_],  g_olo[(size_t)B_*N_*E_];
__device__ float g_bias[(size_t)B_*H_*N_*N_];

// ================= helpers =================
__device__ __forceinline__ uint32_t smem_u32(const void* p) {
    uint32_t a;
    asm("{ .reg .u64 t; cvta.to.shared.u64 t, %1; cvt.u32.u64 %0, t; }" : "=r"(a) : "l"(p));
    return a;
}
__device__ __forceinline__ void ldsm4(uint32_t* r, uint32_t addr) {
    asm volatile("ldmatrix.sync.aligned.m8n8.x4.shared.b16 {%0,%1,%2,%3}, [%4];"
        : "=r"(r[0]), "=r"(r[1]), "=r"(r[2]), "=r"(r[3]) : "r"(addr));
}
__device__ __forceinline__ void ldsm4t(uint32_t* r, uint32_t addr) {
    asm volatile("ldmatrix.sync.aligned.m8n8.x4.trans.shared.b16 {%0,%1,%2,%3}, [%4];"
        : "=r"(r[0]), "=r"(r[1]), "=r"(r[2]), "=r"(r[3]) : "r"(addr));
}
__device__ __forceinline__ void mma16816(float* c, const uint32_t* a, const uint32_t* b) {
    asm volatile("mma.sync.aligned.m16n8k16.row.col.f32.bf16.bf16.f32 "
        "{%0,%1,%2,%3}, {%4,%5,%6,%7}, {%8,%9}, {%0,%1,%2,%3};"
        : "+f"(c[0]), "+f"(c[1]), "+f"(c[2]), "+f"(c[3])
        : "r"(a[0]), "r"(a[1]), "r"(a[2]), "r"(a[3]), "r"(b[0]), "r"(b[1]));
}
__device__ __forceinline__ void split2(float x, float y,
                                       __nv_bfloat162& hi, __nv_bfloat162& lo) {
    __nv_bfloat16 hx = __float2bfloat16(x), hy = __float2bfloat16(y);
    hi.x = hx; hi.y = hy;
    lo.x = __float2bfloat16(x - __bfloat162float(hx));
    lo.y = __float2bfloat16(y - __bfloat162float(hy));
}
__device__ __forceinline__ void pksplit(float x, float y, uint32_t& hi, uint32_t& lo) {
    __nv_bfloat162 H, L;
    split2(x, y, H, L);
    hi = *reinterpret_cast<uint32_t*>(&H);
    lo = *reinterpret_cast<uint32_t*>(&L);
}
#define CP16(dst, src) asm volatile("cp.async.cg.shared.global [%0], [%1], 16;" :: "r"(dst), "l"(src))
#define CPCOMMIT()     asm volatile("cp.async.commit_group;" ::: "memory")
#define CPWAIT0()      asm volatile("cp.async.wait_group 0;" ::: "memory")

// ---------------- prep: fp32->bf16 hi/lo split only ----------------
#define NX4 (B_*N_*E_/4)
#define NWQ4 (3*E_*E_/4)
#define NWO4 (E_*E_/4)
#define CONV_BLOCKS ((NX4+NWQ4+NWO4)/256)

__global__ void prep_kernel(const float4* __restrict__ x4,
                            const float4* __restrict__ wq4,
                            const float4* __restrict__ wo4) {
    int idx = blockIdx.x * blockDim.x + threadIdx.x;
    const float4* src;
    __nv_bfloat162 *hi, *lo;
    int li;
    if (idx < NX4)           { src = x4;  li = idx;              hi = (__nv_bfloat162*)g_xhi;  lo = (__nv_bfloat162*)g_xlo; }
    else if (idx < NX4+NWQ4) { src = wq4; li = idx - NX4;        hi = (__nv_bfloat162*)g_wqhi; lo = (__nv_bfloat162*)g_wqlo; }
    else                     { src = wo4; li = idx - NX4 - NWQ4; hi = (__nv_bfloat162*)g_wohi; lo = (__nv_bfloat162*)g_wolo; }
    float4 v = src[li];
    __nv_bfloat162 h0, l0, h1, l1;
    split2(v.x, v.y, h0, l0); split2(v.z, v.w, h1, l1);
    hi[li*2] = h0; hi[li*2+1] = h1;
    lo[li*2] = l0; lo[li*2+1] = l1;
}

// ======= HMMA GEMM + (mode 0) interleaved bias-tensor CTAs =======
// mode 0: 1D grid of 11-block groups: 8 bias blocks + 3 gemm blocks each.
//   2816 = 256 groups -> 2048 bias blocks (1024 elems each) + 768 gemm blocks.
// mode 1: plain 2D grid, gemm only.
#define TK 32
#define NKS (KDIM/TK)
#define MAT_B (128*40*2)
#define STG_B (4*MAT_B)
#define GEMM_SMEM (2*STG_B)
#define QKV_GRID (11*256)

__global__ __launch_bounds__(256, 2)
void gemm_mma(const float* __restrict__ bias, int mode, float* __restrict__ out,
              const float* __restrict__ U, const float* __restrict__ w_u,
              const float* __restrict__ b_u) {
    extern __shared__ char dsm[];
    const int t    = threadIdx.x;
    const int lane = t & 31;
    const int wid  = t >> 5;

    int bx, by;
    if (mode == 0) {
        int grp = blockIdx.x / 11, rem = blockIdx.x - grp*11;
        if (rem < 8) {
            // ---- bias block: 1024 elements of g_bias from U ----
            float* sw = (float*)dsm;          // 64 w_u + 8 b_u
            if (t < H_*ID_) sw[t] = __ldg(w_u + t);
            if (t < H_)     sw[64 + t] = __ldg(b_u + t);
            __syncthreads();
            int base = (grp*8 + rem) * 1024;
            #pragma unroll
            for (int l = 0; l < 4; l++) {
                int e = base + l*256 + t;                  // element in [0, B*N*N)
                const float4* up = (const float4*)(U + (size_t)e * ID_);
                float4 u0 = __ldg(up), u1 = __ldg(up + 1);
                int b  = e >> 16;                          // / N^2
                int nm = e & 65535;
                #pragma unroll
                for (int h = 0; h < H_; h++) {
                    const float* w = sw + h*ID_;
                    float s = sw[64 + h]
                        + u0.x*w[0] + u0.y*w[1] + u0.z*w[2] + u0.w*w[3]
                        + u1.x*w[4] + u1.y*w[5] + u1.z*w[6] + u1.w*w[7];
                    g_bias[((size_t)(b*H_ + h) << 16) + nm] = s;
                }
            }
            return;
        }
        int g = grp*3 + (rem - 8);            // 0..767
        bx = g % 12; by = g / 12;
    } else {
        bx = blockIdx.x; by = blockIdx.y;
    }

    const int warpM = wid >> 2;
    const int warpN = wid & 3;
    const int rowBase = by * 128;
    const int colBase = bx * 128;
    const uint32_t smb = smem_u32(dsm);

    const __nv_bfloat16 *Ah, *Al, *Wh, *Wl;
    if (mode == 0) { Ah = g_xhi; Al = g_xlo; Wh = g_wqhi; Wl = g_wqlo; }
    else           { Ah = g_ohi; Al = g_olo; Wh = g_wohi; Wl = g_wolo; }

    float acc[4][4][4];
    #pragma unroll
    for (int i = 0; i < 4; i++)
        #pragma unroll
        for (int j = 0; j < 4; j++)
            #pragma unroll
            for (int e = 0; e < 4; e++) acc[i][j][e] = 0.f;

    auto issue = [&](int s) {
        int k0 = s * TK;
        uint32_t st = smb + (s & 1)*STG_B;
        #pragma unroll
        for (int l = 0; l < 2; l++) {
            int f = t + l*256;
            int r = f >> 2, c = f & 3;
            uint32_t doff = (uint32_t)(r*80 + c*16);
            CP16(st + doff,           Ah + (size_t)(rowBase + r)*KDIM + k0 + c*8);
            CP16(st + MAT_B + doff,   Al + (size_t)(rowBase + r)*KDIM + k0 + c*8);
            CP16(st + 2*MAT_B + doff, Wh + (size_t)(colBase + r)*KDIM + k0 + c*8);
            CP16(st + 3*MAT_B + doff, Wl + (size_t)(colBase + r)*KDIM + k0 + c*8);
        }
    };

    issue(0);
    CPCOMMIT();

    for (int ks = 0; ks < NKS; ks++) {
        CPWAIT0();
        __syncthreads();
        if (ks + 1 < NKS) { issue(ks + 1); CPCOMMIT(); }

        uint32_t stg = smb + (ks & 1)*STG_B;
        #pragma unroll
        for (int k16 = 0; k16 < 2; k16++) {
            int colb = k16 * 16;
            uint32_t whi[4][2], wlo[4][2];
            {
                int l8  = lane & 7, sel = lane >> 3;
                #pragma unroll
                for (int np = 0; np < 2; np++) {
                    int wrow = warpN*32 + np*16 + (sel >> 1)*8 + l8;
                    int wcol = colb + (sel & 1)*8;
                    uint32_t off = (uint32_t)(wrow*80 + wcol*2);
                    uint32_t r[4];
                    ldsm4(r, stg + 2*MAT_B + off);
                    whi[np*2+0][0]=r[0]; whi[np*2+0][1]=r[1];
                    whi[np*2+1][0]=r[2]; whi[np*2+1][1]=r[3];
                    ldsm4(r, stg + 3*MAT_B + off);
                    wlo[np*2+0][0]=r[0]; wlo[np*2+0][1]=r[1];
                    wlo[np*2+1][0]=r[2]; wlo[np*2+1][1]=r[3];
                }
            }
            int r8 = lane & 7, half = (lane >> 3) & 1, kk = lane >> 4;
            #pragma unroll
            for (int mi = 0; mi < 4; mi++) {
                int arow = warpM*64 + mi*16 + half*8 + r8;
                int acol = colb + kk*8;
                uint32_t off = (uint32_t)(arow*80 + acol*2);
                uint32_t a[4];
                ldsm4(a, stg + off);
                #pragma unroll
                for (int ni = 0; ni < 4; ni++) mma16816(acc[mi][ni], a, whi[ni]);
                #pragma unroll
                for (int ni = 0; ni < 4; ni++) mma16816(acc[mi][ni], a, wlo[ni]);
                ldsm4(a, stg + MAT_B + off);
                #pragma unroll
                for (int ni = 0; ni < 4; ni++) mma16816(acc[mi][ni], a, whi[ni]);
            }
        }
    }

    const int gID = lane >> 2, tg = lane & 3;
    #pragma unroll
    for (int mi = 0; mi < 4; mi++) {
        #pragma unroll
        for (int ni = 0; ni < 4; ni++) {
            #pragma unroll
            for (int e2 = 0; e2 < 2; e2++) {
                int r = rowBase + warpM*64 + mi*16 + gID + e2*8;
                int c = colBase + warpN*32 + ni*8 + tg*2;
                float v0 = acc[mi][ni][e2*2+0] + __ldg(bias + c);
                float v1 = acc[mi][ni][e2*2+1] + __ldg(bias + c + 1);
                if (mode == 0) {
                    int bb = r >> 8, n = r & 255;
                    int sec = c >> 9;
                    int jj  = c & 511;
                    int h = jj >> 6, d = jj & 63;
                    size_t dst = ((size_t)((bb*H_ + h)*N_ + n))*D_ + d;
                    __nv_bfloat162 hi, lo;
                    if (sec == 0) {
                        split2(v0 * 0.125f, v1 * 0.125f, hi, lo);
                        *(__nv_bfloat162*)(g_qhi + dst) = hi;
                        *(__nv_bfloat162*)(g_qlo + dst) = lo;
                    } else if (sec == 1) {
                        split2(v0, v1, hi, lo);
                        *(__nv_bfloat162*)(g_khi + dst) = hi;
                        *(__nv_bfloat162*)(g_klo + dst) = lo;
                    } else {
                        split2(v0, v1, hi, lo);
                        *(__nv_bfloat162*)(g_vhi + dst) = hi;
                        *(__nv_bfloat162*)(g_vlo + dst) = lo;
                    }
                } else {
                    out[(size_t)r*E_ + c]     = v0;
                    out[(size_t)r*E_ + c + 1] = v1;
                }
            }
        }
    }
}

// ======== attention (R14): online softmax, 2 key chunks, 2 CTAs/SM, g_bias ========
#define KP 72
#define AT_KHI 0
#define AT_KLO 18432
#define AT_VHI 36864
#define AT_VLO 55296
#define AT_QHI 73728
#define AT_QLO 92160
#define ATTN_SMEM 110592

__global__ __launch_bounds__(256, 2)
void attn_kernel() {
    extern __shared__ char asm_[];
    const int bh = blockIdx.x;
    const int q0 = blockIdx.y << 7;
    const int t  = threadIdx.x;
    const int lane = t & 31;
    const int wid  = t >> 5;
    const int gID = lane >> 2, tg = lane & 3;
    const int b  = bh >> 3, h = bh & 7;
    const uint32_t smb = smem_u32(asm_);

    const uint4* khi = (const uint4*)(g_khi + (size_t)bh * N_ * D_);
    const uint4* klo = (const uint4*)(g_klo + (size_t)bh * N_ * D_);
    const uint4* vhi = (const uint4*)(g_vhi + (size_t)bh * N_ * D_);
    const uint4* vlo = (const uint4*)(g_vlo + (size_t)bh * N_ * D_);
    const uint4* qhi = (const uint4*)(g_qhi + (size_t)bh * N_ * D_ + (size_t)q0 * D_);
    const uint4* qlo = (const uint4*)(g_qlo + (size_t)bh * N_ * D_ + (size_t)q0 * D_);
    const float* bbase = g_bias + (size_t)bh * N_ * N_;

    for (int f = t; f < 1024; f += 256) {
        int row = f >> 3, c8 = f & 7;
        int off = row*144 + c8*16;
        *(uint4*)(asm_ + AT_QHI + off) = qhi[f];
        *(uint4*)(asm_ + AT_QLO + off) = qlo[f];
        *(uint4*)(asm_ + AT_KHI + off) = khi[f];
        *(uint4*)(asm_ + AT_KLO + off) = klo[f];
        *(uint4*)(asm_ + AT_VHI + off) = vhi[f];
        *(uint4*)(asm_ + AT_VLO + off) = vlo[f];
    }
    __syncthreads();

    const int l8 = lane & 7, sel = lane >> 3;
    const int r8 = lane & 7, halfq = (lane >> 3) & 1, k8 = lane >> 4;

    float oacc[8][4];
    #pragma unroll
    for (int j = 0; j < 8; j++)
        #pragma unroll
        for (int e = 0; e < 4; e++) oacc[j][e] = 0.f;
    float m_run[2] = { -1e30f, -1e30f };
    float s_run[2] = { 0.f, 0.f };

    #pragma unroll 1
    for (int c = 0; c < 2; c++) {
        float acc[16][4];
        #pragma unroll
        for (int j = 0; j < 16; j++)
            #pragma unroll
            for (int e = 0; e < 4; e++) acc[j][e] = 0.f;

        #pragma unroll
        for (int kk = 0; kk < 4; kk++) {
            int arow = wid*16 + halfq*8 + r8;
            int acol = kk*16 + k8*8;
            uint32_t aoff = (uint32_t)((arow*KP + acol)*2);
            uint32_t ahi[4], alo[4];
            ldsm4(ahi, smb + AT_QHI + aoff);
            ldsm4(alo, smb + AT_QLO + aoff);
            #pragma unroll
            for (int np = 0; np < 8; np++) {
                int wrow = np*16 + (sel >> 1)*8 + l8;
                int wcol = kk*16 + (sel & 1)*8;
                uint32_t koff = (uint32_t)((wrow*KP + wcol)*2);
                uint32_t kf[4];
                ldsm4(kf, smb + AT_KHI + koff);
                mma16816(acc[np*2+0], ahi, kf);
                mma16816(acc[np*2+1], ahi, kf + 2);
                mma16816(acc[np*2+0], alo, kf);
                mma16816(acc[np*2+1], alo, kf + 2);
                ldsm4(kf, smb + AT_KLO + koff);
                mma16816(acc[np*2+0], ahi, kf);
                mma16816(acc[np*2+1], ahi, kf + 2);
            }
        }

        {
            int r0 = q0 + wid*16 + gID;
            int cb = c*128;
            #pragma unroll
            for (int nj = 0; nj < 16; nj++) {
                int cc = cb + nj*8 + tg*2;
                float2 b0 = *(const float2*)(bbase + (size_t)r0*N_ + cc);
                float2 b1 = *(const float2*)(bbase + (size_t)(r0+8)*N_ + cc);
                acc[nj][0] += b0.x; acc[nj][1] += b0.y;
                acc[nj][2] += b1.x; acc[nj][3] += b1.y;
            }
        }

        float scale[2];
        #pragma unroll
        for (int h2 = 0; h2 < 2; h2++) {
            float m = m_run[h2];
            #pragma unroll
            for (int nj = 0; nj < 16; nj++) {
                m = fmaxf(m, acc[nj][h2*2+0]);
                m = fmaxf(m, acc[nj][h2*2+1]);
            }
            m = fmaxf(m, __shfl_xor_sync(0xffffffffu, m, 1));
            m = fmaxf(m, __shfl_xor_sync(0xffffffffu, m, 2));
            scale[h2] = __expf(m_run[h2] - m);
            float s = 0.f;
            #pragma unroll
            for (int nj = 0; nj < 16; nj++) {
                float p0 = __expf(acc[nj][h2*2+0] - m);
                float p1 = __expf(acc[nj][h2*2+1] - m);
                acc[nj][h2*2+0] = p0; acc[nj][h2*2+1] = p1;
                s += p0 + p1;
            }
            s += __shfl_xor_sync(0xffffffffu, s, 1);
            s += __shfl_xor_sync(0xffffffffu, s, 2);
            s_run[h2] = s_run[h2] * scale[h2] + s;
            m_run[h2] = m;
        }
        #pragma unroll
        for (int nd = 0; nd < 8; nd++) {
            oacc[nd][0] *= scale[0]; oacc[nd][1] *= scale[0];
            oacc[nd][2] *= scale[1]; oacc[nd][3] *= scale[1];
        }

        uint32_t (*pk)[4] = reinterpret_cast<uint32_t(*)[4]>(acc);
        #pragma unroll
        for (int nj = 0; nj < 16; nj++) {
            float c0 = acc[nj][0], c1 = acc[nj][1], c2 = acc[nj][2], c3 = acc[nj][3];
            uint32_t h01, l01, h23, l23;
            pksplit(c0, c1, h01, l01);
            pksplit(c2, c3, h23, l23);
            pk[nj][0] = h01; pk[nj][1] = h23; pk[nj][2] = l01; pk[nj][3] = l23;
        }

        #pragma unroll
        for (int kc = 0; kc < 8; kc++) {
            uint32_t pa[4] = { pk[2*kc][0], pk[2*kc][1], pk[2*kc+1][0], pk[2*kc+1][1] };
            uint32_t pl[4] = { pk[2*kc][2], pk[2*kc][3], pk[2*kc+1][2], pk[2*kc+1][3] };
            #pragma unroll
            for (int ng = 0; ng < 4; ng++) {
                int vrow = kc*16 + (sel & 1)*8 + l8;
                int vcol = ng*16 + (sel >> 1)*8;
                uint32_t voff = (uint32_t)((vrow*KP + vcol)*2);
                uint32_t vh[4], vl[4];
                ldsm4t(vh, smb + AT_VHI + voff);
                ldsm4t(vl, smb + AT_VLO + voff);
                #pragma unroll
                for (int j = 0; j < 2; j++) {
                    mma16816(oacc[ng*2+j], pa, vh + j*2);
                    mma16816(oacc[ng*2+j], pa, vl + j*2);
                    mma16816(oacc[ng*2+j], pl, vh + j*2);
                }
            }
        }

        if (c == 0) {
            __syncthreads();
            for (int f = t; f < 1024; f += 256) {
                int row = f >> 3, c8 = f & 7;
                int off = row*144 + c8*16;
                *(uint4*)(asm_ + AT_KHI + off) = khi[1024 + f];
                *(uint4*)(asm_ + AT_KLO + off) = klo[1024 + f];
                *(uint4*)(asm_ + AT_VHI + off) = vhi[1024 + f];
                *(uint4*)(asm_ + AT_VLO + off) = vlo[1024 + f];
            }
            __syncthreads();
        }
    }

    {
        float inv0 = 1.0f / s_run[0], inv1 = 1.0f / s_run[1];
        size_t row0 = (size_t)(b*N_ + q0 + wid*16 + gID) * E_ + h*D_;
        size_t row1 = row0 + 8*E_;
        #pragma unroll
        for (int nd = 0; nd < 8; nd++) {
            int cc = nd*8 + tg*2;
            __nv_bfloat162 h0, l0;
            split2(oacc[nd][0]*inv0, oacc[nd][1]*inv0, h0, l0);
            *(__nv_bfloat162*)(g_ohi + row0 + cc) = h0;
            *(__nv_bfloat162*)(g_olo + row0 + cc) = l0;
            split2(oacc[nd][2]*inv1, oacc[nd][3]*inv1, h0, l0);
            *(__nv_bfloat162*)(g_ohi + row1 + cc) = h0;
            *(__nv_bfloat162*)(g_olo + row1 + cc) = l0;
        }
    }
}

// ---------------- launcher (sequential, default stream) ----------------
extern "C" void kernel_launch(void* const* d_in, const int* in_sizes, int n_in,
                              void* d_out, int out_size) {
    const float* x     = (const float*)d_in[0];
    const float* U     = (const float*)d_in[1];
    const float* w_qkv = (const float*)d_in[2];
    const float* b_qkv = (const float*)d_in[3];
    const float* w_out = (const float*)d_in[4];
    const float* b_out = (const float*)d_in[5];
    const float* w_u   = (const float*)d_in[6];
    const float* b_u   = (const float*)d_in[7];
    float* out = (float*)d_out;

    cudaFuncSetAttribute(gemm_mma, cudaFuncAttributeMaxDynamicSharedMemorySize, GEMM_SMEM);
    cudaFuncSetAttribute(attn_kernel, cudaFuncAttributeMaxDynamicSharedMemorySize, ATTN_SMEM);

    prep_kernel<<<CONV_BLOCKS, 256>>>((const float4*)x,
                                      (const float4*)w_qkv,
                                      (const float4*)w_out);

    // QKV gemm + interleaved bias-tensor blocks (overlapping DRAM & tensor work)
    gemm_mma<<<QKV_GRID, 256, GEMM_SMEM>>>(b_qkv, 0, nullptr, U, w_u, b_u);

    { dim3 g(B_*H_, 2); attn_kernel<<<g, 256, ATTN_SMEM>>>(); }

    { dim3 g(512/128, (B_*N_)/128); gemm_mma<<<g, 256, GEMM_SMEM>>>(b_out, 1, out, nullptr, nullptr, nullptr); }
}